// round 4
// baseline (speedup 1.0000x reference)
#include <cuda_runtime.h>
#include <math.h>

#define USER_NUM 100000
#define ITEM_NUM 50000
#define FACTOR   64
#define NQ       16          // FACTOR/4 float4 per row
#define EDGES    3200000
#define BATCH    4096
#define LAMADA   0.0001

// ---------------- scratch (device globals, no allocation) ----------------
__device__ float4 g_gcn1_u[(size_t)USER_NUM * NQ];
__device__ float4 g_gcn1_i[(size_t)ITEM_NUM * NQ];
__device__ float4 g_gcn2_u[(size_t)USER_NUM * NQ];
__device__ float4 g_gcn2_i[(size_t)ITEM_NUM * NQ];
__device__ unsigned char g_uflag[USER_NUM];
__device__ unsigned char g_iflag[ITEM_NUM];
__device__ double g_acc[2];   // [0]=sum softplus, [1]=sum squares

// ---------------- vector RED helper ----------------
__device__ __forceinline__ void red_add4(float4* p, float4 v) {
#if __CUDA_ARCH__ >= 900
    atomicAdd(p, v);          // compiles to RED.E.ADD.v4.F32
#else
    float* f = (float*)p;
    atomicAdd(f + 0, v.x); atomicAdd(f + 1, v.y);
    atomicAdd(f + 2, v.z); atomicAdd(f + 3, v.w);
#endif
}

// ---------------- K0: zero flags + accumulators ----------------
__global__ void k_zero() {
    int g = blockIdx.x * blockDim.x + threadIdx.x;
    if (g < USER_NUM) g_uflag[g] = 0;
    else if (g < USER_NUM + ITEM_NUM) g_iflag[g - USER_NUM] = 0;
    if (g < 2) g_acc[g] = 0.0;
}

// ---------------- K1: set batch flags ----------------
__global__ void k_setflags(const int* __restrict__ user,
                           const int* __restrict__ item_i,
                           const int* __restrict__ item_j) {
    int g = blockIdx.x * blockDim.x + threadIdx.x;
    if (g < BATCH)          g_uflag[user[g]]            = 1;
    else if (g < 2 * BATCH) g_iflag[item_i[g - BATCH]]  = 1;
    else if (g < 3 * BATCH) g_iflag[item_j[g - 2*BATCH]] = 1;
}

// ---------------- K2: gcn1 = embed * d (full init) ----------------
__global__ void k_init1(const float4* __restrict__ eu, const float4* __restrict__ ei,
                        const float* __restrict__ d_i, const float* __restrict__ d_j) {
    int g = blockIdx.x * blockDim.x + threadIdx.x;
    if (g < USER_NUM * NQ) {
        float s = __ldg(&d_i[g >> 4]);
        float4 v = __ldg(&eu[g]);
        g_gcn1_u[g] = make_float4(v.x * s, v.y * s, v.z * s, v.w * s);
    } else if (g < (USER_NUM + ITEM_NUM) * NQ) {
        int gi = g - USER_NUM * NQ;
        float s = __ldg(&d_j[gi >> 4]);
        float4 v = __ldg(&ei[gi]);
        g_gcn1_i[gi] = make_float4(v.x * s, v.y * s, v.z * s, v.w * s);
    }
}

// ---------------- K3: edge pass 1 (full scatter, both directions) ------
__global__ void k_edges1(const int* __restrict__ u_idx, const int* __restrict__ i_idx,
                         const float* __restrict__ ui_vals, const float* __restrict__ iu_vals,
                         const float4* __restrict__ eu, const float4* __restrict__ ei) {
    unsigned gid = blockIdx.x * blockDim.x + threadIdx.x;
    unsigned e = gid >> 4;
    if (e >= EDGES) return;
    unsigned q = gid & 15u;
    int u = __ldg(&u_idx[e]);
    int i = __ldg(&i_idx[e]);
    float ui = __ldg(&ui_vals[e]);
    float iu = __ldg(&iu_vals[e]);
    float4 vi = __ldg(&ei[(size_t)i * NQ + q]);   // item row chunk
    float4 vu = __ldg(&eu[(size_t)u * NQ + q]);   // user row chunk
    red_add4(&g_gcn1_u[(size_t)u * NQ + q],
             make_float4(vi.x * ui, vi.y * ui, vi.z * ui, vi.w * ui));
    red_add4(&g_gcn1_i[(size_t)i * NQ + q],
             make_float4(vu.x * iu, vu.y * iu, vu.z * iu, vu.w * iu));
}

// ---------------- K4: init gcn2 only at batch rows ----------------
__global__ void k_init2(const int* __restrict__ user,
                        const int* __restrict__ item_i,
                        const int* __restrict__ item_j,
                        const float* __restrict__ d_i, const float* __restrict__ d_j) {
    int g = blockIdx.x * blockDim.x + threadIdx.x;   // 3*BATCH*NQ threads
    int b = g >> 4, q = g & 15;
    if (b < BATCH) {
        int u = __ldg(&user[b]);
        float s = __ldg(&d_i[u]);
        float4 v = g_gcn1_u[(size_t)u * NQ + q];
        g_gcn2_u[(size_t)u * NQ + q] = make_float4(v.x*s, v.y*s, v.z*s, v.w*s);
    } else if (b < 3 * BATCH) {
        int i = (b < 2 * BATCH) ? __ldg(&item_i[b - BATCH]) : __ldg(&item_j[b - 2*BATCH]);
        float s = __ldg(&d_j[i]);
        float4 v = g_gcn1_i[(size_t)i * NQ + q];
        g_gcn2_i[(size_t)i * NQ + q] = make_float4(v.x*s, v.y*s, v.z*s, v.w*s);
    }
}

// ---------------- K5: edge pass 2, masked to flagged targets ----------
__global__ void k_edges2(const int* __restrict__ u_idx, const int* __restrict__ i_idx,
                         const float* __restrict__ ui_vals, const float* __restrict__ iu_vals) {
    unsigned gid = blockIdx.x * blockDim.x + threadIdx.x;
    unsigned e = gid >> 4;
    if (e >= EDGES) return;
    unsigned q = gid & 15u;
    int u = __ldg(&u_idx[e]);
    int i = __ldg(&i_idx[e]);
    unsigned char fu = g_uflag[u];
    unsigned char fi = g_iflag[i];
    if (!fu && !fi) return;
    if (fu) {
        float ui = __ldg(&ui_vals[e]);
        float4 v = g_gcn1_i[(size_t)i * NQ + q];
        red_add4(&g_gcn2_u[(size_t)u * NQ + q],
                 make_float4(v.x*ui, v.y*ui, v.z*ui, v.w*ui));
    }
    if (fi) {
        float iu = __ldg(&iu_vals[e]);
        float4 v = g_gcn1_u[(size_t)u * NQ + q];
        red_add4(&g_gcn2_i[(size_t)i * NQ + q],
                 make_float4(v.x*iu, v.y*iu, v.z*iu, v.w*iu));
    }
}

// ---------------- K6: batch gather + loss reduction ----------------
__device__ __forceinline__ float2 ld3(const float* a, const float* b, const float* c, size_t off) {
    float2 x = *(const float2*)(a + off);
    float2 y = *(const float2*)(b + off);
    float2 z = *(const float2*)(c + off);
    return make_float2(x.x + y.x + z.x, x.y + y.y + z.y);
}

__global__ void k_final(const float* __restrict__ eu, const float* __restrict__ ei,
                        const int* __restrict__ user,
                        const int* __restrict__ item_i, const int* __restrict__ item_j) {
    const float* g1u = (const float*)g_gcn1_u;
    const float* g2u = (const float*)g_gcn2_u;
    const float* g1i = (const float*)g_gcn1_i;
    const float* g2i = (const float*)g_gcn2_i;

    int lane = threadIdx.x & 31;
    int warp = (blockIdx.x * blockDim.x + threadIdx.x) >> 5;
    int nwarp = (gridDim.x * blockDim.x) >> 5;

    double l_loss = 0.0, l_sq = 0.0;
    for (int b = warp; b < BATCH; b += nwarp) {
        int u  = __ldg(&user[b]);
        int pi = __ldg(&item_i[b]);
        int pj = __ldg(&item_j[b]);
        size_t du = (size_t)u  * FACTOR + 2 * lane;
        size_t di = (size_t)pi * FACTOR + 2 * lane;
        size_t dj = (size_t)pj * FACTOR + 2 * lane;
        float2 U  = ld3(eu, g1u, g2u, du);
        float2 Pi = ld3(ei, g1i, g2i, di);
        float2 Pj = ld3(ei, g1i, g2i, dj);
        float dot_i = U.x * Pi.x + U.y * Pi.y;
        float dot_j = U.x * Pj.x + U.y * Pj.y;
        float sq = U.x*U.x + U.y*U.y + Pi.x*Pi.x + Pi.y*Pi.y + Pj.x*Pj.x + Pj.y*Pj.y;
        #pragma unroll
        for (int o = 16; o; o >>= 1) {
            dot_i += __shfl_xor_sync(0xFFFFFFFFu, dot_i, o);
            dot_j += __shfl_xor_sync(0xFFFFFFFFu, dot_j, o);
            sq    += __shfl_xor_sync(0xFFFFFFFFu, sq, o);
        }
        if (lane == 0) {
            float z = dot_j - dot_i;                 // -(pred_i - pred_j)
            float sp = fmaxf(z, 0.0f) + log1pf(expf(-fabsf(z)));
            l_loss += (double)sp;
            l_sq   += (double)sq;
        }
    }
    // block reduce (lane0 of each warp holds partials)
    __shared__ double s_loss[8], s_sq[8];
    int wib = threadIdx.x >> 5;
    if (lane == 0) { s_loss[wib] = l_loss; s_sq[wib] = l_sq; }
    __syncthreads();
    if (threadIdx.x == 0) {
        double tl = 0.0, ts = 0.0;
        int nw = blockDim.x >> 5;
        for (int w = 0; w < nw; w++) { tl += s_loss[w]; ts += s_sq[w]; }
        atomicAdd(&g_acc[0], tl);
        atomicAdd(&g_acc[1], ts);
    }
}

// ---------------- K7: finalize scalar ----------------
__global__ void k_write(float* out) {
    if (threadIdx.x == 0 && blockIdx.x == 0) {
        double loss = g_acc[0] / (double)BATCH
                    + LAMADA * g_acc[1] / ((double)BATCH * (double)FACTOR);
        out[0] = (float)loss;
    }
}

// ---------------- launch ----------------
extern "C" void kernel_launch(void* const* d_in, const int* in_sizes, int n_in,
                              void* d_out, int out_size) {
    const float* embed_user = (const float*)d_in[0];
    const float* embed_item = (const float*)d_in[1];
    const int*   u_idx      = (const int*)d_in[2];
    const int*   i_idx      = (const int*)d_in[3];
    const float* ui_vals    = (const float*)d_in[4];
    const float* iu_vals    = (const float*)d_in[5];
    const float* d_i        = (const float*)d_in[6];
    const float* d_j        = (const float*)d_in[7];
    const int*   user       = (const int*)d_in[8];
    const int*   item_i     = (const int*)d_in[9];
    const int*   item_j     = (const int*)d_in[10];
    float* out = (float*)d_out;

    const float4* eu4 = (const float4*)embed_user;
    const float4* ei4 = (const float4*)embed_item;

    // K0: zero flags + acc
    {
        int n = USER_NUM + ITEM_NUM;
        k_zero<<<(n + 255) / 256, 256>>>();
    }
    // K1: set flags
    k_setflags<<<(3 * BATCH + 255) / 256, 256>>>(user, item_i, item_j);
    // K2: gcn1 init
    {
        int n = (USER_NUM + ITEM_NUM) * NQ;
        k_init1<<<(n + 255) / 256, 256>>>(eu4, ei4, d_i, d_j);
    }
    // K3: edge pass 1
    {
        long long n = (long long)EDGES * NQ;
        k_edges1<<<(unsigned)((n + 255) / 256), 256>>>(u_idx, i_idx, ui_vals, iu_vals, eu4, ei4);
    }
    // K4: gcn2 init at batch rows
    {
        int n = 3 * BATCH * NQ;
        k_init2<<<(n + 255) / 256, 256>>>(user, item_i, item_j, d_i, d_j);
    }
    // K5: edge pass 2 (masked)
    {
        long long n = (long long)EDGES * NQ;
        k_edges2<<<(unsigned)((n + 255) / 256), 256>>>(u_idx, i_idx, ui_vals, iu_vals);
    }
    // K6: loss
    k_final<<<32, 256>>>(embed_user, embed_item, user, item_i, item_j);
    // K7: write scalar
    k_write<<<1, 32>>>(out);

    (void)in_sizes; (void)n_in; (void)out_size;
}

// round 5
// speedup vs baseline: 1.5789x; 1.5789x over previous
#include <cuda_runtime.h>
#include <math.h>

#define USER_NUM 100000
#define ITEM_NUM 50000
#define FACTOR   64
#define NQ       16          // FACTOR/4 float4 per row
#define EDGES    3200000
#define BATCH    4096
#define LAMADA   0.0001

// ---------------- scratch (device globals, no allocation) ----------------
__device__ float4 g_gcn1_u[(size_t)USER_NUM * NQ];      // 25.6 MB
__device__ float4 g_gcn1_i[(size_t)ITEM_NUM * NQ];      // 12.8 MB
__device__ int2   g_csr_u[EDGES];                       // 25.6 MB  {i_idx, ui_val}
__device__ int2   g_csr_i[EDGES];                       // 25.6 MB  {u_idx, iu_val}
__device__ int    g_deg_u[USER_NUM];
__device__ int    g_deg_i[ITEM_NUM];
__device__ int    g_rp_u[USER_NUM + 1];
__device__ int    g_rp_i[ITEM_NUM + 1];
__device__ int    g_cur_u[USER_NUM];
__device__ int    g_cur_i[ITEM_NUM];
__device__ float4 g_brow[(size_t)3 * BATCH * NQ];       // gathered final rows: u / pi / pj
__device__ double g_acc[2];                             // [0]=sum softplus, [1]=sum squares

// ---------------- K0: clear degree counters + accumulators ----------------
__global__ void k_clear() {
    int g = blockIdx.x * blockDim.x + threadIdx.x;
    if (g < USER_NUM) g_deg_u[g] = 0;
    else if (g < USER_NUM + ITEM_NUM) g_deg_i[g - USER_NUM] = 0;
    if (g < 2) g_acc[g] = 0.0;
}

// ---------------- K1: degree histogram ----------------
__global__ void k_hist(const int* __restrict__ u_idx, const int* __restrict__ i_idx) {
    int e = blockIdx.x * blockDim.x + threadIdx.x;
    if (e >= EDGES) return;
    atomicAdd(&g_deg_u[__ldg(&u_idx[e])], 1);
    atomicAdd(&g_deg_i[__ldg(&i_idx[e])], 1);
}

// ---------------- K2: exclusive scan -> row_ptr + cursor (2 blocks) ------
__global__ void k_scan() {
    const bool isU = (blockIdx.x == 0);
    const int  N   = isU ? USER_NUM : ITEM_NUM;
    int* deg = isU ? g_deg_u : g_deg_i;
    int* rp  = isU ? g_rp_u  : g_rp_i;
    int* cur = isU ? g_cur_u : g_cur_i;

    __shared__ int wsum[32];
    int lane = threadIdx.x & 31, wid = threadIdx.x >> 5;
    int carry = 0;

    for (int base = 0; base < N; base += 1024) {
        int idx = base + threadIdx.x;
        int v = (idx < N) ? deg[idx] : 0;
        int x = v;
        #pragma unroll
        for (int o = 1; o < 32; o <<= 1) {
            int y = __shfl_up_sync(0xFFFFFFFFu, x, o);
            if (lane >= o) x += y;
        }
        if (lane == 31) wsum[wid] = x;
        __syncthreads();
        if (wid == 0) {
            int s = wsum[lane];
            #pragma unroll
            for (int o = 1; o < 32; o <<= 1) {
                int y = __shfl_up_sync(0xFFFFFFFFu, s, o);
                if (lane >= o) s += y;
            }
            wsum[lane] = s;
        }
        __syncthreads();
        int woff = wid ? wsum[wid - 1] : 0;
        int excl = carry + woff + x - v;
        if (idx < N) { rp[idx] = excl; cur[idx] = excl; }
        carry += wsum[31];
        __syncthreads();
    }
    if (threadIdx.x == 0) rp[N] = EDGES;
}

// ---------------- K3: scatter edges into both CSRs ----------------
__global__ void k_scatter(const int* __restrict__ u_idx, const int* __restrict__ i_idx,
                          const float* __restrict__ ui_vals, const float* __restrict__ iu_vals) {
    int e = blockIdx.x * blockDim.x + threadIdx.x;
    if (e >= EDGES) return;
    int u = __ldg(&u_idx[e]);
    int i = __ldg(&i_idx[e]);
    int pu = atomicAdd(&g_cur_u[u], 1);
    g_csr_u[pu] = make_int2(i, __float_as_int(__ldg(&ui_vals[e])));
    int pi = atomicAdd(&g_cur_i[i], 1);
    g_csr_i[pi] = make_int2(u, __float_as_int(__ldg(&iu_vals[e])));
}

// ---------------- K4: layer-1 gather SpMM (fused u & i directions) -------
__global__ void k_gcn1(const float4* __restrict__ eu, const float4* __restrict__ ei,
                       const float* __restrict__ d_i, const float* __restrict__ d_j) {
    unsigned gid = blockIdx.x * blockDim.x + threadIdx.x;
    unsigned r = gid >> 4, q = gid & 15u;
    if (r < USER_NUM) {
        float s = __ldg(&d_i[r]);
        float4 acc = __ldg(&eu[(size_t)r * NQ + q]);
        acc.x *= s; acc.y *= s; acc.z *= s; acc.w *= s;
        int e = __ldg(&g_rp_u[r]), end = __ldg(&g_rp_u[r + 1]);
        #pragma unroll 4
        for (; e < end; e++) {
            int2 pr = __ldg(&g_csr_u[e]);
            float v = __int_as_float(pr.y);
            float4 w = __ldg(&ei[(size_t)pr.x * NQ + q]);
            acc.x += w.x * v; acc.y += w.y * v; acc.z += w.z * v; acc.w += w.w * v;
        }
        g_gcn1_u[(size_t)r * NQ + q] = acc;
    } else if (r < USER_NUM + ITEM_NUM) {
        unsigned ri = r - USER_NUM;
        float s = __ldg(&d_j[ri]);
        float4 acc = __ldg(&ei[(size_t)ri * NQ + q]);
        acc.x *= s; acc.y *= s; acc.z *= s; acc.w *= s;
        int e = __ldg(&g_rp_i[ri]), end = __ldg(&g_rp_i[ri + 1]);
        #pragma unroll 4
        for (; e < end; e++) {
            int2 pr = __ldg(&g_csr_i[e]);
            float v = __int_as_float(pr.y);
            float4 w = __ldg(&eu[(size_t)pr.x * NQ + q]);
            acc.x += w.x * v; acc.y += w.y * v; acc.z += w.z * v; acc.w += w.w * v;
        }
        g_gcn1_i[(size_t)ri * NQ + q] = acc;
    }
}

// ---------------- K5: layer-2 only at batch entries, write final rows -----
// g_brow[slot] = embed + gcn1 + gcn2 at the batch-referenced row.
__global__ void k_batch(const float4* __restrict__ eu, const float4* __restrict__ ei,
                        const float* __restrict__ d_i, const float* __restrict__ d_j,
                        const int* __restrict__ user,
                        const int* __restrict__ item_i, const int* __restrict__ item_j) {
    unsigned gid = blockIdx.x * blockDim.x + threadIdx.x;
    unsigned slot = gid >> 4, q = gid & 15u;
    if (slot >= 3 * BATCH) return;

    if (slot < BATCH) {
        int u = __ldg(&user[slot]);
        float s = __ldg(&d_i[u]);
        float4 g1 = g_gcn1_u[(size_t)u * NQ + q];
        // gcn2_u = gcn1_u*di + sum gcn1_i[i]*ui ; final = eu + g1 + gcn2
        float4 acc = make_float4(g1.x * s, g1.y * s, g1.z * s, g1.w * s);
        int e = __ldg(&g_rp_u[u]), end = __ldg(&g_rp_u[u + 1]);
        #pragma unroll 4
        for (; e < end; e++) {
            int2 pr = __ldg(&g_csr_u[e]);
            float v = __int_as_float(pr.y);
            float4 w = g_gcn1_i[(size_t)pr.x * NQ + q];
            acc.x += w.x * v; acc.y += w.y * v; acc.z += w.z * v; acc.w += w.w * v;
        }
        float4 e0 = __ldg(&eu[(size_t)u * NQ + q]);
        g_brow[(size_t)slot * NQ + q] =
            make_float4(e0.x + g1.x + acc.x, e0.y + g1.y + acc.y,
                        e0.z + g1.z + acc.z, e0.w + g1.w + acc.w);
    } else {
        unsigned b = slot - BATCH;
        int i = (b < BATCH) ? __ldg(&item_i[b]) : __ldg(&item_j[b - BATCH]);
        float s = __ldg(&d_j[i]);
        float4 g1 = g_gcn1_i[(size_t)i * NQ + q];
        float4 acc = make_float4(g1.x * s, g1.y * s, g1.z * s, g1.w * s);
        int e = __ldg(&g_rp_i[i]), end = __ldg(&g_rp_i[i + 1]);
        #pragma unroll 4
        for (; e < end; e++) {
            int2 pr = __ldg(&g_csr_i[e]);
            float v = __int_as_float(pr.y);
            float4 w = g_gcn1_u[(size_t)pr.x * NQ + q];
            acc.x += w.x * v; acc.y += w.y * v; acc.z += w.z * v; acc.w += w.w * v;
        }
        float4 e0 = __ldg(&ei[(size_t)i * NQ + q]);
        g_brow[(size_t)slot * NQ + q] =
            make_float4(e0.x + g1.x + acc.x, e0.y + g1.y + acc.y,
                        e0.z + g1.z + acc.z, e0.w + g1.w + acc.w);
    }
}

// ---------------- K6: loss reduction ----------------
__global__ void k_final() {
    const float* rows = (const float*)g_brow;
    int lane = threadIdx.x & 31;
    int warp = (blockIdx.x * blockDim.x + threadIdx.x) >> 5;
    int nwarp = (gridDim.x * blockDim.x) >> 5;

    double l_loss = 0.0, l_sq = 0.0;
    for (int b = warp; b < BATCH; b += nwarp) {
        size_t du = (size_t)b * FACTOR + 2 * lane;
        size_t di = (size_t)(BATCH + b) * FACTOR + 2 * lane;
        size_t dj = (size_t)(2 * BATCH + b) * FACTOR + 2 * lane;
        float2 U  = *(const float2*)(rows + du);
        float2 Pi = *(const float2*)(rows + di);
        float2 Pj = *(const float2*)(rows + dj);
        float dot_i = U.x * Pi.x + U.y * Pi.y;
        float dot_j = U.x * Pj.x + U.y * Pj.y;
        float sq = U.x*U.x + U.y*U.y + Pi.x*Pi.x + Pi.y*Pi.y + Pj.x*Pj.x + Pj.y*Pj.y;
        #pragma unroll
        for (int o = 16; o; o >>= 1) {
            dot_i += __shfl_xor_sync(0xFFFFFFFFu, dot_i, o);
            dot_j += __shfl_xor_sync(0xFFFFFFFFu, dot_j, o);
            sq    += __shfl_xor_sync(0xFFFFFFFFu, sq, o);
        }
        if (lane == 0) {
            float z = dot_j - dot_i;                 // -(pred_i - pred_j)
            float sp = fmaxf(z, 0.0f) + log1pf(expf(-fabsf(z)));
            l_loss += (double)sp;
            l_sq   += (double)sq;
        }
    }
    __shared__ double s_loss[8], s_sq[8];
    int wib = threadIdx.x >> 5;
    if (lane == 0) { s_loss[wib] = l_loss; s_sq[wib] = l_sq; }
    __syncthreads();
    if (threadIdx.x == 0) {
        double tl = 0.0, ts = 0.0;
        int nw = blockDim.x >> 5;
        for (int w = 0; w < nw; w++) { tl += s_loss[w]; ts += s_sq[w]; }
        atomicAdd(&g_acc[0], tl);
        atomicAdd(&g_acc[1], ts);
    }
}

// ---------------- K7: finalize scalar ----------------
__global__ void k_write(float* out) {
    if (threadIdx.x == 0 && blockIdx.x == 0) {
        double loss = g_acc[0] / (double)BATCH
                    + LAMADA * g_acc[1] / ((double)BATCH * (double)FACTOR);
        out[0] = (float)loss;
    }
}

// ---------------- launch ----------------
extern "C" void kernel_launch(void* const* d_in, const int* in_sizes, int n_in,
                              void* d_out, int out_size) {
    const float* embed_user = (const float*)d_in[0];
    const float* embed_item = (const float*)d_in[1];
    const int*   u_idx      = (const int*)d_in[2];
    const int*   i_idx      = (const int*)d_in[3];
    const float* ui_vals    = (const float*)d_in[4];
    const float* iu_vals    = (const float*)d_in[5];
    const float* d_i        = (const float*)d_in[6];
    const float* d_j        = (const float*)d_in[7];
    const int*   user       = (const int*)d_in[8];
    const int*   item_i     = (const int*)d_in[9];
    const int*   item_j     = (const int*)d_in[10];
    float* out = (float*)d_out;

    const float4* eu4 = (const float4*)embed_user;
    const float4* ei4 = (const float4*)embed_item;

    // K0: clear counters
    {
        int n = USER_NUM + ITEM_NUM;
        k_clear<<<(n + 255) / 256, 256>>>();
    }
    // K1: degree histogram
    k_hist<<<(EDGES + 511) / 512, 512>>>(u_idx, i_idx);
    // K2: scan -> row_ptr + cursors
    k_scan<<<2, 1024>>>();
    // K3: scatter to CSR (both directions)
    k_scatter<<<(EDGES + 511) / 512, 512>>>(u_idx, i_idx, ui_vals, iu_vals);
    // K4: layer-1 gather SpMM (fused user+item)
    {
        long long n = (long long)(USER_NUM + ITEM_NUM) * NQ;
        k_gcn1<<<(unsigned)((n + 255) / 256), 256>>>(eu4, ei4, d_i, d_j);
    }
    // K5: layer-2 gather at batch rows only, producing final gathered rows
    {
        int n = 3 * BATCH * NQ;
        k_batch<<<(n + 255) / 256, 256>>>(eu4, ei4, d_i, d_j, user, item_i, item_j);
    }
    // K6: loss
    k_final<<<32, 256>>>();
    // K7: write scalar
    k_write<<<1, 32>>>(out);

    (void)in_sizes; (void)n_in; (void)out_size;
}